// round 17
// baseline (speedup 1.0000x reference)
#include <cuda_runtime.h>
#include <cuda_bf16.h>
#include <math.h>
#include <stdint.h>

#define BB 8
#define CIN 256
#define CC 128
#define HW 16384
#define NSPLIT 32
#define SCHUNK 512

#define KPAD 40
#define NPAD 136
#define A2PAD 136
#define HA_STG (128 * KPAD)      // 5120 elems
#define HB_STG (32 * NPAD)       // 4352 elems

// chain kernel smem layout (bf16 elems); A pipeline = 4 stages
#define ASTAGES 4
#define AS_OFF 0
#define BS_OFF (AS_OFF + ASTAGES * HA_STG)    // 20480
#define P1_ELEMS (BS_OFF + 2 * HB_STG)        // 29184
#define A2_OFF 0
#define B2_OFF P1_ELEMS                        // 29184
#define CHAIN_ELEMS (B2_OFF + 128 * NPAD)      // 46592
#define CHAIN_SM_BYTES (CHAIN_ELEMS * 2)       // 93184

// s_bf: 4-stage cp.async pipeline
#define SSTAGES 4
#define SSTG_ELEMS (2 * HA_STG)
#define SSM_BYTES (SSTAGES * SSTG_ELEMS * 2)   // 81920

// out_bf v3: single tile, dual cp.async
#define OA_OFF 0
#define OB_OFF (128 * A2PAD)                   // 17408
#define O_ELEMS (OB_OFF + 128 * NPAD)          // 34816
#define OSM_BYTES (O_ELEMS * 2 + 256 * 4)      // 70656

// ---------------- scratch ----------------
__device__ __nv_bfloat16 g_wkvh[2 * CC * CIN];
__device__ __nv_bfloat16 g_wq1h[CC * CIN];
__device__ __nv_bfloat16 g_wq2h[CC * CC];
__device__ __nv_bfloat16 g_wk2h[CC * CC];
__device__ float g_bkv[2 * CC], g_bq1[CC], g_bq2[CC], g_bk2[CC];
__device__ __nv_bfloat16 g_val[(size_t)BB * CC * HW];
__device__ __nv_bfloat16 g_key[(size_t)BB * CC * HW];
__device__ __nv_bfloat16 g_qr [(size_t)BB * CC * HW];
__device__ float g_S[BB * CC * CC];
__device__ __nv_bfloat16 g_Sbf[BB * CC * CC];
__device__ float g_Z[BB * CC];

// ---------------- helpers ----------------
__device__ __forceinline__ void st4h(__nv_bfloat16* p, float4 v) {
    __nv_bfloat162 lo = __floats2bfloat162_rn(v.x, v.y);
    __nv_bfloat162 hi = __floats2bfloat162_rn(v.z, v.w);
    uint2 u = { *(uint32_t*)&lo, *(uint32_t*)&hi };
    *(uint2*)p = u;
}
__device__ __forceinline__ void ldsm4(uint32_t* r, uint32_t a) {
    asm volatile("ldmatrix.sync.aligned.m8n8.x4.shared.b16 {%0,%1,%2,%3}, [%4];"
                 : "=r"(r[0]), "=r"(r[1]), "=r"(r[2]), "=r"(r[3]) : "r"(a));
}
__device__ __forceinline__ void ldsm4t(uint32_t* r, uint32_t a) {
    asm volatile("ldmatrix.sync.aligned.m8n8.x4.trans.shared.b16 {%0,%1,%2,%3}, [%4];"
                 : "=r"(r[0]), "=r"(r[1]), "=r"(r[2]), "=r"(r[3]) : "r"(a));
}
__device__ __forceinline__ void mma16(float* c, const uint32_t* a, const uint32_t* b) {
    asm volatile("mma.sync.aligned.m16n8k16.row.col.f32.bf16.bf16.f32 "
                 "{%0,%1,%2,%3}, {%4,%5,%6,%7}, {%8,%9}, {%0,%1,%2,%3};"
                 : "+f"(c[0]), "+f"(c[1]), "+f"(c[2]), "+f"(c[3])
                 : "r"(a[0]), "r"(a[1]), "r"(a[2]), "r"(a[3]), "r"(b[0]), "r"(b[1]));
}
__device__ __forceinline__ void cpa16(uint32_t dst, const void* src) {
    asm volatile("cp.async.cg.shared.global [%0], [%1], 16;" :: "r"(dst), "l"(src));
}
#define CPA_COMMIT() asm volatile("cp.async.commit_group;" ::: "memory")
#define CPA_WAIT0()  asm volatile("cp.async.wait_group 0;" ::: "memory")
#define CPA_WAIT1()  asm volatile("cp.async.wait_group 1;" ::: "memory")
#define CPA_WAIT2()  asm volatile("cp.async.wait_group 2;" ::: "memory")
__device__ __forceinline__ float softplus_fast(float x) {
    return fmaxf(x, 0.f) + log1pf(__expf(-fabsf(x)));
}

// ---------------- merged BN fold (weights -> bf16) ----------------
struct PrepEnt { const float *w, *g, *b, *m, *v; __nv_bfloat16* wf; float* bf; int K; };
struct PrepAll { PrepEnt e[5]; };

__global__ void fold5(PrepAll a) {
    PrepEnt p = a.e[blockIdx.y];
    int o = blockIdx.x;
    float s = p.g[o] * rsqrtf(p.v[o] + 1e-5f);
    if (threadIdx.x == 0) p.bf[o] = p.b[o] - p.m[o] * s;
    for (int c = threadIdx.x; c < p.K; c += blockDim.x)
        p.wf[o * p.K + c] = __float2bfloat16(p.w[o * p.K + c] * s);
}

// ---------------- S fp32 -> bf16 ----------------
__global__ void s2bf(const float* __restrict__ S, __nv_bfloat16* __restrict__ Sb) {
    int i = (blockIdx.x * 256 + threadIdx.x) * 4;
    float4 v = *(const float4*)(S + i);
    st4h(Sb + i, v);
}

__device__ __forceinline__ void zero_acc(float acc[2][8][4]) {
#pragma unroll
    for (int i = 0; i < 2; i++)
#pragma unroll
        for (int j = 0; j < 8; j++)
#pragma unroll
            for (int l = 0; l < 4; l++) acc[i][j][l] = 0.f;
}

// ---------------- phase-1: A bf16 4-stage cp.async, B fp32 reg-prefetch ----
__device__ __forceinline__ void mainloop1(float acc[2][8][4], __nv_bfloat16* hsm,
                                          uint32_t sbase, const __nv_bfloat16* Ab,
                                          const float* Xb, int tid, int wm, int wn,
                                          uint32_t aLane, uint32_t bLane) {
    __nv_bfloat16* Bs = hsm + BS_OFF;
    const int bk = tid >> 5, bn = (tid & 31) * 4;
    auto fillA = [&](int stage, int k0) {
        uint32_t dst = sbase + (AS_OFF + stage * HA_STG) * 2;
#pragma unroll
        for (int t = 0; t < 2; t++) {
            int id = tid + t * 256;
            int row = id >> 2, k8 = (id & 3) * 8;
            cpa16(dst + (row * KPAD + k8) * 2, Ab + (size_t)row * CIN + k0 + k8);
        }
        CPA_COMMIT();
    };
    fillA(0, 0);
    fillA(1, 32);
    fillA(2, 64);
#pragma unroll
    for (int i = 0; i < 4; i++) {
        int k = bk + 8 * i;
        float4 v = *(const float4*)(Xb + (size_t)k * HW + bn);
        st4h(Bs + k * NPAD + bn, v);
    }
    CPA_WAIT2();
    __syncthreads();

    constexpr int NKB = CIN / 32;
    for (int kb = 0; kb < NKB; kb++) {
        if (kb + 3 < NKB) fillA((kb + 3) & (ASTAGES - 1), (kb + 3) * 32);
        float4 rb[4];
        if (kb + 1 < NKB) {
            const int k0 = (kb + 1) * 32;
#pragma unroll
            for (int i = 0; i < 4; i++)
                rb[i] = *(const float4*)(Xb + (size_t)(k0 + bk + 8 * i) * HW + bn);
        }
        const uint32_t sA = sbase + (AS_OFF + (kb & (ASTAGES - 1)) * HA_STG) * 2;
        const uint32_t sB = sbase + (BS_OFF + (kb & 1) * HB_STG) * 2;
#pragma unroll
        for (int kk = 0; kk < 2; kk++) {
            uint32_t a[2][4], bq[8][2];
#pragma unroll
            for (int mw = 0; mw < 2; mw++)
                ldsm4(a[mw], sA + ((wm * 32 + mw * 16) * KPAD) * 2 + kk * 32 + aLane);
#pragma unroll
            for (int ng = 0; ng < 4; ng++) {
                uint32_t r[4];
                ldsm4t(r, sB + (kk * 16 * NPAD + wn * 64 + ng * 16) * 2 + bLane);
                bq[2 * ng][0] = r[0]; bq[2 * ng][1] = r[1];
                bq[2 * ng + 1][0] = r[2]; bq[2 * ng + 1][1] = r[3];
            }
#pragma unroll
            for (int mw = 0; mw < 2; mw++)
#pragma unroll
                for (int nw = 0; nw < 8; nw++)
                    mma16(acc[mw][nw], a[mw], bq[nw]);
        }
        if (kb + 1 < NKB) {
            __nv_bfloat16* Bd = Bs + ((kb + 1) & 1) * HB_STG;
#pragma unroll
            for (int i = 0; i < 4; i++)
                st4h(Bd + (bk + 8 * i) * NPAD + bn, rb[i]);
            const int rem = NKB - 2 - kb;
            if (rem >= 2)      CPA_WAIT2();
            else if (rem == 1) CPA_WAIT1();
            else               CPA_WAIT0();
        }
        __syncthreads();
    }
}

// ---------------- smem-resident K=128 mainloop ----------------
__device__ __forceinline__ void mainloop2p(float acc[2][8][4], uint32_t sbase,
                                           uint32_t a_off_b, uint32_t b_off_b,
                                           int wm, int wn, uint32_t aLane2,
                                           uint32_t bLane) {
    const uint32_t sA2 = sbase + a_off_b;
    const uint32_t sB2 = sbase + b_off_b;
#pragma unroll
    for (int kb = 0; kb < 4; kb++) {
#pragma unroll
        for (int kk = 0; kk < 2; kk++) {
            const int kofs = kb * 32 + kk * 16;
            uint32_t a[2][4], bq[8][2];
#pragma unroll
            for (int mw = 0; mw < 2; mw++)
                ldsm4(a[mw], sA2 + ((wm * 32 + mw * 16) * A2PAD + kofs) * 2 + aLane2);
#pragma unroll
            for (int ng = 0; ng < 4; ng++) {
                uint32_t r[4];
                ldsm4t(r, sB2 + ((size_t)kofs * NPAD + wn * 64 + ng * 16) * 2 + bLane);
                bq[2 * ng][0] = r[0]; bq[2 * ng][1] = r[1];
                bq[2 * ng + 1][0] = r[2]; bq[2 * ng + 1][1] = r[3];
            }
#pragma unroll
            for (int mw = 0; mw < 2; mw++)
#pragma unroll
                for (int nw = 0; nw < 8; nw++)
                    mma16(acc[mw][nw], a[mw], bq[nw]);
        }
    }
}

// ---------------- chain body ----------------
__device__ __forceinline__ void chain_body(__nv_bfloat16* hsm, uint32_t sbase,
                                           const __nv_bfloat16* W1, const float* b1,
                                           const __nv_bfloat16* W2, const float* b2,
                                           const float* Xb, __nv_bfloat16* Yout,
                                           int tid, int wm, int wn, int qid, int tq,
                                           uint32_t aLane, uint32_t bLane) {
    const int lane = tid & 31;
    const uint32_t aLane2 = ((lane & 15) * A2PAD + (lane >> 4) * 8) * 2;

    float acc[2][8][4];
    zero_acc(acc);
    mainloop1(acc, hsm, sbase, W1, Xb, tid, wm, wn, aLane, bLane);

    {
        uint32_t dst = sbase + A2_OFF * 2;
#pragma unroll
        for (int t = 0; t < 8; t++) {
            int id = tid + t * 256;
            int m = id >> 4, k8 = (id & 15) * 8;
            cpa16(dst + (m * A2PAD + k8) * 2, W2 + (size_t)m * CC + k8);
        }
        CPA_COMMIT();
    }
    {
        __nv_bfloat16* B2s = hsm + B2_OFF;
#pragma unroll
        for (int mw = 0; mw < 2; mw++) {
            const int r0 = wm * 32 + mw * 16 + qid;
            float bv0 = b1[r0], bv1 = b1[r0 + 8];
#pragma unroll
            for (int nw = 0; nw < 8; nw++) {
                const int col = wn * 64 + nw * 8 + tq * 2;
                __nv_bfloat162 p0 = __floats2bfloat162_rn(
                    fmaxf(acc[mw][nw][0] + bv0, 0.f), fmaxf(acc[mw][nw][1] + bv0, 0.f));
                __nv_bfloat162 p1 = __floats2bfloat162_rn(
                    fmaxf(acc[mw][nw][2] + bv1, 0.f), fmaxf(acc[mw][nw][3] + bv1, 0.f));
                *(__nv_bfloat162*)(B2s + (size_t)r0 * NPAD + col) = p0;
                *(__nv_bfloat162*)(B2s + (size_t)(r0 + 8) * NPAD + col) = p1;
            }
        }
    }
    CPA_WAIT0();
    __syncthreads();

    zero_acc(acc);
    mainloop2p(acc, sbase, A2_OFF * 2, B2_OFF * 2, wm, wn, aLane2, bLane);

#pragma unroll
    for (int mw = 0; mw < 2; mw++) {
        const int r0 = wm * 32 + mw * 16 + qid;
        float bv0 = b2[r0], bv1 = b2[r0 + 8];
#pragma unroll
        for (int nw = 0; nw < 8; nw++) {
            const int col = wn * 64 + nw * 8 + tq * 2;
            __nv_bfloat162 p0 = __floats2bfloat162_rn(
                softplus_fast(acc[mw][nw][0] + bv0), softplus_fast(acc[mw][nw][1] + bv0));
            __nv_bfloat162 p1 = __floats2bfloat162_rn(
                softplus_fast(acc[mw][nw][2] + bv1), softplus_fast(acc[mw][nw][3] + bv1));
            *(__nv_bfloat162*)(Yout + (size_t)r0 * HW + col) = p0;
            *(__nv_bfloat162*)(Yout + (size_t)(r0 + 8) * HW + col) = p1;
        }
    }
}

// ---------------- merged conv kernel ----------------
__global__ void __launch_bounds__(256, 2)
conv_all(const __nv_bfloat16* __restrict__ Wkv, const float* __restrict__ bkv,
         const __nv_bfloat16* __restrict__ Wk2, const float* __restrict__ bk2,
         const __nv_bfloat16* __restrict__ Wq1, const float* __restrict__ bq1,
         const __nv_bfloat16* __restrict__ Wq2, const float* __restrict__ bq2,
         const float* __restrict__ Xsrc, const float* __restrict__ Xtgt,
         __nv_bfloat16* __restrict__ val, __nv_bfloat16* __restrict__ key,
         __nv_bfloat16* __restrict__ qr) {
    extern __shared__ __nv_bfloat16 hsm[];
    const int tid = threadIdx.x;
    const int b = blockIdx.y;
    const int role = blockIdx.x % 3;
    const int n0 = (blockIdx.x / 3) * 128;
    const int warp = tid >> 5, lane = tid & 31;
    const int wm = warp >> 1, wn = warp & 1;
    const int qid = lane >> 2, tq = lane & 3;
    const uint32_t sbase = (uint32_t)__cvta_generic_to_shared(hsm);
    const uint32_t aLane = ((lane & 15) * KPAD + (lane >> 4) * 8) * 2;
    const uint32_t bLane = ((lane & 15) * NPAD + (lane >> 4) * 8) * 2;

    if (role == 1) {
        const float* Xb = Xsrc + (size_t)b * CIN * HW + n0;
        float acc[2][8][4];
        zero_acc(acc);
        mainloop1(acc, hsm, sbase, Wkv + (size_t)128 * CIN, Xb, tid, wm, wn, aLane, bLane);
        __nv_bfloat16* Yb = val + (size_t)b * CC * HW + n0;
        const float* bp = bkv + 128;
#pragma unroll
        for (int mw = 0; mw < 2; mw++) {
            const int r0 = wm * 32 + mw * 16 + qid;
            float bv0 = bp[r0], bv1 = bp[r0 + 8];
#pragma unroll
            for (int nw = 0; nw < 8; nw++) {
                const int col = wn * 64 + nw * 8 + tq * 2;
                __nv_bfloat162 p0 = __floats2bfloat162_rn(
                    fmaxf(acc[mw][nw][0] + bv0, 0.f), fmaxf(acc[mw][nw][1] + bv0, 0.f));
                __nv_bfloat162 p1 = __floats2bfloat162_rn(
                    fmaxf(acc[mw][nw][2] + bv1, 0.f), fmaxf(acc[mw][nw][3] + bv1, 0.f));
                *(__nv_bfloat162*)(Yb + (size_t)r0 * HW + col) = p0;
                *(__nv_bfloat162*)(Yb + (size_t)(r0 + 8) * HW + col) = p1;
            }
        }
    } else if (role == 0) {
        chain_body(hsm, sbase, Wkv, bkv, Wk2, bk2,
                   Xsrc + (size_t)b * CIN * HW + n0,
                   key + (size_t)b * CC * HW + n0, tid, wm, wn, qid, tq, aLane, bLane);
    } else {
        chain_body(hsm, sbase, Wq1, bq1, Wq2, bq2,
                   Xtgt + (size_t)b * CIN * HW + n0,
                   qr + (size_t)b * CC * HW + n0, tid, wm, wn, qid, tq, aLane, bLane);
    }
}

// ============================================================================
// S[b,c,d] += sum_n V K^T (+ fused Z), 4-stage cp.async pipeline
// ============================================================================
__global__ void __launch_bounds__(256, 2)
s_bf(const __nv_bfloat16* __restrict__ V, const __nv_bfloat16* __restrict__ Kt,
     float* __restrict__ S, float* __restrict__ Z) {
    extern __shared__ __nv_bfloat16 hsm[];
    const int tid = threadIdx.x;
    const int b = blockIdx.y;
    const int n0 = blockIdx.x * SCHUNK;
    const int warp = tid >> 5, lane = tid & 31;
    const int wm = warp >> 1, wn = warp & 1;
    const int qid = lane >> 2, tq = lane & 3;
    const __nv_bfloat16* Vb = V + (size_t)b * CC * HW + n0;
    const __nv_bfloat16* Kb = Kt + (size_t)b * CC * HW + n0;
    constexpr int NKB = SCHUNK / 32;

    float acc[2][8][4];
    zero_acc(acc);
    float zp[2] = {0.f, 0.f};
    const uint32_t sbase = (uint32_t)__cvta_generic_to_shared(hsm);
    const uint32_t lLane = ((lane & 15) * KPAD + (lane >> 4) * 8) * 2;
    const int frow = tid >> 2;
    const int fk8 = (tid & 3) * 8;

    auto issue_fill = [&](int stage, int k0) {
        uint32_t vdst = sbase + (stage * SSTG_ELEMS) * 2;
        uint32_t kdst = vdst + HA_STG * 2;
#pragma unroll
        for (int t = 0; t < 2; t++) {
            int row = frow + 64 * t;
            cpa16(vdst + (row * KPAD + fk8) * 2, Vb + (size_t)row * HW + k0 + fk8);
            cpa16(kdst + (row * KPAD + fk8) * 2, Kb + (size_t)row * HW + k0 + fk8);
        }
        CPA_COMMIT();
    };

    issue_fill(0, 0);
    issue_fill(1, 32);
    issue_fill(2, 64);

    for (int kb = 0; kb < NKB; kb++) {
        if (kb < NKB - 2)       CPA_WAIT2();
        else if (kb == NKB - 2) CPA_WAIT1();
        else                    CPA_WAIT0();
        __syncthreads();
        if (kb + 3 < NKB) issue_fill((kb + 3) & (SSTAGES - 1), (kb + 3) * 32);

        const int st = kb & (SSTAGES - 1);
        {
            const __nv_bfloat16* Kd = hsm + st * SSTG_ELEMS + HA_STG;
#pragma unroll
            for (int t = 0; t < 2; t++) {
                int row = frow + 64 * t;
                uint4 kv4 = *(const uint4*)(Kd + row * KPAD + fk8);
                const __nv_bfloat162* h = (const __nv_bfloat162*)&kv4;
#pragma unroll
                for (int j = 0; j < 4; j++) {
                    float2 f2 = __bfloat1622float2(h[j]);
                    zp[t] += f2.x + f2.y;
                }
            }
        }
        const uint32_t sA = sbase + (st * SSTG_ELEMS) * 2;
        const uint32_t sB = sA + HA_STG * 2;
#pragma unroll
        for (int kk = 0; kk < 2; kk++) {
            uint32_t a[2][4], bq[8][2];
#pragma unroll
            for (int mw = 0; mw < 2; mw++)
                ldsm4(a[mw], sA + ((wm * 32 + mw * 16) * KPAD) * 2 + kk * 32 + lLane);
#pragma unroll
            for (int ng = 0; ng < 4; ng++) {
                uint32_t r[4];
                ldsm4(r, sB + ((wn * 64 + ng * 16) * KPAD) * 2 + kk * 32 + lLane);
                bq[2 * ng][0] = r[0]; bq[2 * ng][1] = r[2];
                bq[2 * ng + 1][0] = r[1]; bq[2 * ng + 1][1] = r[3];
            }
#pragma unroll
            for (int mw = 0; mw < 2; mw++)
#pragma unroll
                for (int nw = 0; nw < 8; nw++)
                    mma16(acc[mw][nw], a[mw], bq[nw]);
        }
        __syncthreads();
    }

#pragma unroll
    for (int o = 1; o < 4; o <<= 1) {
        zp[0] += __shfl_xor_sync(0xffffffff, zp[0], o);
        zp[1] += __shfl_xor_sync(0xffffffff, zp[1], o);
    }
    if ((lane & 3) == 0) {
        atomicAdd(&Z[b * CC + (tid >> 2)], zp[0]);
        atomicAdd(&Z[b * CC + 64 + (tid >> 2)], zp[1]);
    }

    float* Sb = S + (size_t)b * CC * CC;
#pragma unroll
    for (int mw = 0; mw < 2; mw++) {
        const int r0 = wm * 32 + mw * 16 + qid;
#pragma unroll
        for (int nw = 0; nw < 8; nw++) {
            const int col = wn * 64 + nw * 8 + tq * 2;
            atomicAdd(&Sb[(size_t)r0 * CC + col],           acc[mw][nw][0]);
            atomicAdd(&Sb[(size_t)r0 * CC + col + 1],       acc[mw][nw][1]);
            atomicAdd(&Sb[(size_t)(r0 + 8) * CC + col],     acc[mw][nw][2]);
            atomicAdd(&Sb[(size_t)(r0 + 8) * CC + col + 1], acc[mw][nw][3]);
        }
    }
}

// ============================================================================
// out GEMM v3: single tile, A (S_bf) AND B (q) via cp.async, den fused
// ============================================================================
__global__ void __launch_bounds__(256, 2)
out_bf(const __nv_bfloat16* __restrict__ Sbf, const __nv_bfloat16* __restrict__ Q,
       const float* __restrict__ Zvec, float* __restrict__ Y) {
    extern __shared__ __nv_bfloat16 hsm[];
    float* den_s = (float*)(hsm + O_ELEMS);
    float* Zs = den_s + 128;
    const int tid = threadIdx.x;
    const int b = blockIdx.y;
    const int n0 = blockIdx.x * 128;
    const int warp = tid >> 5, lane = tid & 31;
    const int wm = warp >> 1, wn = warp & 1;
    const int qid = lane >> 2, tq = lane & 3;
    const uint32_t sbase = (uint32_t)__cvta_generic_to_shared(hsm);
    const uint32_t aLane2 = ((lane & 15) * A2PAD + (lane >> 4) * 8) * 2;
    const uint32_t bLane = ((lane & 15) * NPAD + (lane >> 4) * 8) * 2;
    const __nv_bfloat16* Ab = Sbf + (size_t)b * CC * CC;
    const __nv_bfloat16* Xb = Q + (size_t)b * CC * HW + n0;
    const int n8 = (tid & 15) * 8;

    // A: S_bf [128 x 128] -> stride A2PAD, via cp.async
    {
        uint32_t dst = sbase + OA_OFF * 2;
#pragma unroll
        for (int t = 0; t < 8; t++) {
            int id = tid + t * 256;
            int m = id >> 4, k8 = (id & 15) * 8;
            cpa16(dst + (m * A2PAD + k8) * 2, Ab + (size_t)m * CC + k8);
        }
        CPA_COMMIT();
    }
    // B: q tile via cp.async
    {
        uint32_t dst = sbase + OB_OFF * 2;
#pragma unroll
        for (int t = 0; t < 8; t++) {
            int k = (tid >> 4) + t * 16;
            cpa16(dst + (k * NPAD + n8) * 2, Xb + (size_t)k * HW + n8);
        }
        CPA_COMMIT();
    }
    if (tid < 128) { Zs[tid] = Zvec[b * CC + tid]; den_s[tid] = 0.f; }
    CPA_WAIT0();
    __syncthreads();

    // den from smem q
    {
        const __nv_bfloat16* B2s = hsm + OB_OFF;
        float dreg[8] = {0.f, 0.f, 0.f, 0.f, 0.f, 0.f, 0.f, 0.f};
#pragma unroll
        for (int t = 0; t < 8; t++) {
            int k = (tid >> 4) + t * 16;
            uint4 q4 = *(const uint4*)(B2s + (size_t)k * NPAD + n8);
            float z = Zs[k];
            const __nv_bfloat162* h = (const __nv_bfloat162*)&q4;
#pragma unroll
            for (int j = 0; j < 4; j++) {
                float2 f2 = __bfloat1622float2(h[j]);
                dreg[2 * j]     = fmaf(z, f2.x, dreg[2 * j]);
                dreg[2 * j + 1] = fmaf(z, f2.y, dreg[2 * j + 1]);
            }
        }
#pragma unroll
        for (int j = 0; j < 8; j++) atomicAdd(&den_s[n8 + j], dreg[j]);
    }
    __syncthreads();

    float acc[2][8][4];
    zero_acc(acc);
    mainloop2p(acc, sbase, OA_OFF * 2, OB_OFF * 2, wm, wn, aLane2, bLane);

    float* Yb = Y + (size_t)b * CC * HW + n0;
#pragma unroll
    for (int mw = 0; mw < 2; mw++) {
        const int r0 = wm * 32 + mw * 16 + qid;
#pragma unroll
        for (int nw = 0; nw < 8; nw++) {
            const int col = wn * 64 + nw * 8 + tq * 2;
            float i0 = 1.f / fmaxf(den_s[col], 1e-12f);
            float i1 = 1.f / fmaxf(den_s[col + 1], 1e-12f);
            float2 p0 = { acc[mw][nw][0] * i0, acc[mw][nw][1] * i1 };
            float2 p1 = { acc[mw][nw][2] * i0, acc[mw][nw][3] * i1 };
            *(float2*)(Yb + (size_t)r0 * HW + col) = p0;
            *(float2*)(Yb + (size_t)(r0 + 8) * HW + col) = p1;
        }
    }
}

// ---------------- launch ----------------
extern "C" void kernel_launch(void* const* d_in, const int* in_sizes, int n_in,
                              void* d_out, int out_size) {
    const float* target = (const float*)d_in[0];
    const float* source = (const float*)d_in[1];
    const float* q_w1 = (const float*)d_in[2];
    const float* q_w2 = (const float*)d_in[3];
    const float* k_w1 = (const float*)d_in[4];
    const float* k_w2 = (const float*)d_in[5];
    const float* v_w  = (const float*)d_in[6];

    __nv_bfloat16 *wkvh, *wq1h, *wq2h, *wk2h, *val, *key, *qr, *Sbf;
    float *bkv, *bq1, *bq2, *bk2, *S, *Z;
    cudaGetSymbolAddress((void**)&wkvh, g_wkvh);
    cudaGetSymbolAddress((void**)&wq1h, g_wq1h);
    cudaGetSymbolAddress((void**)&wq2h, g_wq2h);
    cudaGetSymbolAddress((void**)&wk2h, g_wk2h);
    cudaGetSymbolAddress((void**)&bkv, g_bkv);
    cudaGetSymbolAddress((void**)&bq1, g_bq1);
    cudaGetSymbolAddress((void**)&bq2, g_bq2);
    cudaGetSymbolAddress((void**)&bk2, g_bk2);
    cudaGetSymbolAddress((void**)&val, g_val);
    cudaGetSymbolAddress((void**)&key, g_key);
    cudaGetSymbolAddress((void**)&qr,  g_qr);
    cudaGetSymbolAddress((void**)&S,   g_S);
    cudaGetSymbolAddress((void**)&Sbf, g_Sbf);
    cudaGetSymbolAddress((void**)&Z,   g_Z);

    cudaFuncSetAttribute(conv_all, cudaFuncAttributeMaxDynamicSharedMemorySize, CHAIN_SM_BYTES);
    cudaFuncSetAttribute(s_bf,  cudaFuncAttributeMaxDynamicSharedMemorySize, SSM_BYTES);
    cudaFuncSetAttribute(out_bf, cudaFuncAttributeMaxDynamicSharedMemorySize, OSM_BYTES);

    PrepAll pa;
    pa.e[0] = { k_w1, (const float*)d_in[15], (const float*)d_in[16], (const float*)d_in[17], (const float*)d_in[18], wkvh, bkv, CIN };
    pa.e[1] = { v_w,  (const float*)d_in[23], (const float*)d_in[24], (const float*)d_in[25], (const float*)d_in[26], wkvh + CC * CIN, bkv + CC, CIN };
    pa.e[2] = { q_w1, (const float*)d_in[7],  (const float*)d_in[8],  (const float*)d_in[9],  (const float*)d_in[10], wq1h, bq1, CIN };
    pa.e[3] = { q_w2, (const float*)d_in[11], (const float*)d_in[12], (const float*)d_in[13], (const float*)d_in[14], wq2h, bq2, CC };
    pa.e[4] = { k_w2, (const float*)d_in[19], (const float*)d_in[20], (const float*)d_in[21], (const float*)d_in[22], wk2h, bk2, CC };
    fold5<<<dim3(CC, 5), 256>>>(pa);

    cudaMemsetAsync(S, 0, BB * CC * CC * sizeof(float));
    cudaMemsetAsync(Z, 0, BB * CC * sizeof(float));

    conv_all<<<dim3(HW / 128 * 3, BB), 256, CHAIN_SM_BYTES>>>(
        wkvh, bkv, wk2h, bk2, wq1h, bq1, wq2h, bq2, source, target, val, key, qr);
    s_bf<<<dim3(NSPLIT, BB), 256, SSM_BYTES>>>(val, key, S, Z);
    s2bf<<<BB * CC * CC / 1024, 256>>>(S, Sbf);
    out_bf<<<dim3(HW / 128, BB), 256, OSM_BYTES>>>(Sbf, qr, Z, (float*)d_out);
}